// round 2
// baseline (speedup 1.0000x reference)
#include <cuda_runtime.h>
#include <cuda_bf16.h>
#include <math.h>

// Problem dims
#define Bv 128
#define Lv 512
#define Dv 512
#define Ev 64
#define Hv 512
#define Vv 17
#define CCH 8              // chains per CTA in the scan

#define FULLMASK 0xffffffffu

// Output layout (float32 concat of the 4 reference outputs)
#define OFF_LOGITS 0
#define OFF_PREDS  (Bv*Lv*Vv)                 // 1114112
#define OFF_PROBS  (OFF_PREDS + Bv*Lv)        // 1179648
#define OFF_EMB    (OFF_PROBS + Bv*Lv*Vv)     // 2293760

// Scratch: pre[b, t, h] = inputs[b,t,:] @ W1[:, :D]^T + b1   (128 MB)
__device__ float g_pre[(size_t)Bv * Lv * Hv];

// ---------------------------------------------------------------------------
// Kernel 1: pre = A @ W1x^T + b1.  (unchanged from R1 — near fp32 FFMA peak)
// ---------------------------------------------------------------------------
__global__ __launch_bounds__(256) void gemm_pre_kernel(
    const float* __restrict__ A, const float* __restrict__ W,
    const float* __restrict__ bias)
{
    constexpr int BM = 128, BN = 128, BK = 16;
    __shared__ float sA[BK][BM + 4];
    __shared__ float sB[BK][BN + 4];

    const int bm = blockIdx.y * BM;
    const int bn = blockIdx.x * BN;
    const int tid = threadIdx.x;
    const int tx = tid & 15;
    const int ty = tid >> 4;

    float acc[8][8];
#pragma unroll
    for (int i = 0; i < 8; i++)
#pragma unroll
        for (int j = 0; j < 8; j++) acc[i][j] = 0.f;

    for (int k0 = 0; k0 < Dv; k0 += BK) {
#pragma unroll
        for (int s = 0; s < 2; s++) {
            int slot = tid + s * 256;
            int r  = slot >> 2;
            int c4 = (slot & 3) * 4;
            float4 va = *reinterpret_cast<const float4*>(
                &A[(size_t)(bm + r) * Dv + k0 + c4]);
            sA[c4 + 0][r] = va.x; sA[c4 + 1][r] = va.y;
            sA[c4 + 2][r] = va.z; sA[c4 + 3][r] = va.w;
            float4 vb = *reinterpret_cast<const float4*>(
                &W[(size_t)(bn + r) * (Dv + Ev) + k0 + c4]);
            sB[c4 + 0][r] = vb.x; sB[c4 + 1][r] = vb.y;
            sB[c4 + 2][r] = vb.z; sB[c4 + 3][r] = vb.w;
        }
        __syncthreads();
#pragma unroll
        for (int k = 0; k < BK; k++) {
            float a[8], b[8];
#pragma unroll
            for (int i = 0; i < 8; i++) a[i] = sA[k][ty * 8 + i];
#pragma unroll
            for (int j = 0; j < 8; j++) b[j] = sB[k][tx * 8 + j];
#pragma unroll
            for (int i = 0; i < 8; i++)
#pragma unroll
                for (int j = 0; j < 8; j++) acc[i][j] += a[i] * b[j];
        }
        __syncthreads();
    }

    float bb[8];
#pragma unroll
    for (int j = 0; j < 8; j++) bb[j] = bias[bn + tx * 8 + j];

#pragma unroll
    for (int i = 0; i < 8; i++) {
        size_t row = (size_t)(bm + ty * 8 + i);
#pragma unroll
        for (int j = 0; j < 8; j += 4) {
            int col = bn + tx * 8 + j;
            float4 v;
            v.x = acc[i][j + 0] + bb[j + 0];
            v.y = acc[i][j + 1] + bb[j + 1];
            v.z = acc[i][j + 2] + bb[j + 2];
            v.w = acc[i][j + 3] + bb[j + 3];
            *reinterpret_cast<float4*>(&g_pre[row * Hv + col]) = v;
        }
    }
}

// ---------------------------------------------------------------------------
// Kernel 2: packed sequential scan. CCH=8 chains per CTA, 16 CTAs, 544 threads
// (17 warps). Serial loop only produces logits + argmax; softmax/embedding
// deferred to post_kernel.
// ---------------------------------------------------------------------------
__global__ __launch_bounds__(544) void scan8_kernel(
    const float* __restrict__ emb_table,   // [V, E]
    const float* __restrict__ W1,          // [H, D+E]
    const float* __restrict__ W2,          // [V, H]
    const float* __restrict__ b2,          // [V]
    float* __restrict__ out)
{
    __shared__ float sM[Vv][Hv];          // table @ W1e^T (34816 B)
    __shared__ float sH[CCH][Hv];         // hidden states (16 KB)
    __shared__ float sLogit[CCH][Vv + 3];
    __shared__ int   sPred[CCH];

    const int b0   = blockIdx.x * CCH;
    const int tid  = threadIdx.x;
    const int w    = tid >> 5;
    const int lane = tid & 31;

    // Precompute M[v][h] = sum_e table[v][e] * W1[h][D+e]; row 0 zero (padding)
    for (int idx = tid; idx < Vv * Hv; idx += 544) {
        int v = idx / Hv, h = idx - v * Hv;
        float acc = 0.f;
        if (v != 0) {
            const float* er = emb_table + v * Ev;
            const float* wr = W1 + (size_t)h * (Dv + Ev) + Dv;
#pragma unroll 8
            for (int e = 0; e < Ev; e++) acc += er[e] * wr[e];
        }
        sM[v][h] = acc;
    }
    if (tid < CCH) sPred[tid] = 0;   // PAD

    // W2 rows in registers: warp w owns logit w
    float w2r[16];
    float bias2 = 0.f;
    if (w < Vv) {
#pragma unroll
        for (int k = 0; k < 16; k++) w2r[k] = W2[(size_t)w * Hv + k * 32 + lane];
        bias2 = b2[w];
    }
    __syncthreads();

    float* outL = out + OFF_LOGITS;
    float* outP = out + OFF_PREDS;

    const float* preT = g_pre + (size_t)b0 * Lv * Hv + tid;  // +c*L*H +t*H

    float pc[CCH], pn[CCH];
    if (tid < Hv) {
#pragma unroll
        for (int c = 0; c < CCH; c++)
            pc[c] = preT[(size_t)c * Lv * Hv];
    }

    for (int t = 0; t < Lv; t++) {
        // prefetch next step's pre slices (latency hidden behind this step)
        if (tid < Hv) {
            size_t off = (size_t)(t + 1) * Hv;
            if (t + 1 < Lv) {
#pragma unroll
                for (int c = 0; c < CCH; c++)
                    pn[c] = preT[(size_t)c * Lv * Hv + off];
            }
        }

        // stage 1: hidden states for all chains
        if (tid < Hv) {
#pragma unroll
            for (int c = 0; c < CCH; c++) {
                int p = sPred[c];
                sH[c][tid] = tanhf(pc[c] + sM[p][tid]);
            }
        }
        __syncthreads();

        // stage 2: warp w computes logit w for all chains
        if (w < Vv) {
            float acc[CCH];
#pragma unroll
            for (int c = 0; c < CCH; c++) acc[c] = 0.f;
#pragma unroll
            for (int k = 0; k < 16; k++) {
                float wv = w2r[k];
#pragma unroll
                for (int c = 0; c < CCH; c++)
                    acc[c] += sH[c][k * 32 + lane] * wv;
            }
#pragma unroll
            for (int off = 16; off; off >>= 1) {
#pragma unroll
                for (int c = 0; c < CCH; c++)
                    acc[c] += __shfl_xor_sync(FULLMASK, acc[c], off);
            }
            if (lane == 0) {
#pragma unroll
                for (int c = 0; c < CCH; c++) {
                    float lg = acc[c] + bias2;
                    sLogit[c][w] = lg;
                    outL[((size_t)(b0 + c) * Lv + t) * Vv + w] = lg;
                }
            }
        }
        __syncthreads();

        // stage 3: warp c argmaxes chain c's 17 logits
        if (w < CCH) {
            float bv = (lane < Vv) ? sLogit[w][lane] : -1e30f;
            int   bi = (lane < Vv) ? lane : Vv;
#pragma unroll
            for (int off = 16; off; off >>= 1) {
                float ov = __shfl_down_sync(FULLMASK, bv, off);
                int   oi = __shfl_down_sync(FULLMASK, bi, off);
                if (ov > bv || (ov == bv && oi < bi)) { bv = ov; bi = oi; }
            }
            if (lane == 0) {
                sPred[w] = bi;
                outP[(size_t)(b0 + w) * Lv + t] = (float)bi;
            }
        }
        __syncthreads();

#pragma unroll
        for (int c = 0; c < CCH; c++) pc[c] = pn[c];
    }
}

// ---------------------------------------------------------------------------
// Kernel 3: parallel post-pass — log-softmax from saved logits, preds_emb.
// One warp per (b,t) row.
// ---------------------------------------------------------------------------
__global__ __launch_bounds__(256) void post_kernel(
    const float* __restrict__ emb_table,
    float* __restrict__ out)
{
    const float* outL = out + OFF_LOGITS;
    const float* outP = out + OFF_PREDS;
    float* outQ  = out + OFF_PROBS;
    float* outEb = out + OFF_EMB;

    const int lane = threadIdx.x & 31;
    const int warps_total = (gridDim.x * blockDim.x) >> 5;
    int gw = (blockIdx.x * blockDim.x + threadIdx.x) >> 5;

    for (int row = gw; row < Bv * Lv; row += warps_total) {
        float v = (lane < Vv) ? outL[(size_t)row * Vv + lane] : -1e30f;
        float m = v;
#pragma unroll
        for (int off = 16; off; off >>= 1)
            m = fmaxf(m, __shfl_xor_sync(FULLMASK, m, off));
        float e = (lane < Vv) ? expf(v - m) : 0.f;
        float s = e;
#pragma unroll
        for (int off = 16; off; off >>= 1)
            s += __shfl_xor_sync(FULLMASK, s, off);
        float lse = m + logf(s);
        if (lane < Vv) outQ[(size_t)row * Vv + lane] = v - lse;

        int pred = (int)outP[row];
        float e0 = (pred != 0) ? emb_table[pred * Ev + lane] : 0.f;
        float e1 = (pred != 0) ? emb_table[pred * Ev + 32 + lane] : 0.f;
        outEb[(size_t)row * Ev + lane]      = e0;
        outEb[(size_t)row * Ev + 32 + lane] = e1;
    }
}

// ---------------------------------------------------------------------------
extern "C" void kernel_launch(void* const* d_in, const int* in_sizes, int n_in,
                              void* d_out, int out_size)
{
    const float* inputs    = (const float*)d_in[0];  // [B, L, D]
    const float* emb_table = (const float*)d_in[1];  // [V, E]
    const float* W1        = (const float*)d_in[2];  // [H, D+E]
    const float* b1        = (const float*)d_in[3];  // [H]
    const float* W2        = (const float*)d_in[4];  // [V, H]
    const float* b2        = (const float*)d_in[5];  // [V]
    float* out = (float*)d_out;

    (void)in_sizes; (void)n_in; (void)out_size;

    dim3 ggrid(Hv / 128, (Bv * Lv) / 128);   // (4, 512)
    gemm_pre_kernel<<<ggrid, 256>>>(inputs, W1, b1);

    scan8_kernel<<<Bv / CCH, 544>>>(emb_table, W1, W2, b2, out);

    post_kernel<<<256, 256>>>(emb_table, out);
}

// round 3
// speedup vs baseline: 1.9042x; 1.9042x over previous
#include <cuda_runtime.h>
#include <cuda_bf16.h>
#include <math.h>

// Problem dims
#define Bv 128
#define Lv 512
#define Dv 512
#define Ev 64
#define Hv 512
#define Vv 17

#define FULLMASK 0xffffffffu

// Output layout (float32 concat of the 4 reference outputs)
#define OFF_LOGITS 0
#define OFF_PREDS  (Bv*Lv*Vv)                 // 1114112
#define OFF_PROBS  (OFF_PREDS + Bv*Lv)        // 1179648
#define OFF_EMB    (OFF_PROBS + Bv*Lv*Vv)     // 2293760

// Scratch: pre[b, t, h] = inputs[b,t,:] @ W1[:, :D]^T + b1   (128 MB)
__device__ float g_pre[(size_t)Bv * Lv * Hv];

// ---------------------------------------------------------------------------
// Kernel 1: pre = A @ W1x^T + b1.  (unchanged — ~57% of fp32 FFMA peak)
// ---------------------------------------------------------------------------
__global__ __launch_bounds__(256) void gemm_pre_kernel(
    const float* __restrict__ A, const float* __restrict__ W,
    const float* __restrict__ bias)
{
    constexpr int BM = 128, BN = 128, BK = 16;
    __shared__ float sA[BK][BM + 4];
    __shared__ float sB[BK][BN + 4];

    const int bm = blockIdx.y * BM;
    const int bn = blockIdx.x * BN;
    const int tid = threadIdx.x;
    const int tx = tid & 15;
    const int ty = tid >> 4;

    float acc[8][8];
#pragma unroll
    for (int i = 0; i < 8; i++)
#pragma unroll
        for (int j = 0; j < 8; j++) acc[i][j] = 0.f;

    for (int k0 = 0; k0 < Dv; k0 += BK) {
#pragma unroll
        for (int s = 0; s < 2; s++) {
            int slot = tid + s * 256;
            int r  = slot >> 2;
            int c4 = (slot & 3) * 4;
            float4 va = *reinterpret_cast<const float4*>(
                &A[(size_t)(bm + r) * Dv + k0 + c4]);
            sA[c4 + 0][r] = va.x; sA[c4 + 1][r] = va.y;
            sA[c4 + 2][r] = va.z; sA[c4 + 3][r] = va.w;
            float4 vb = *reinterpret_cast<const float4*>(
                &W[(size_t)(bn + r) * (Dv + Ev) + k0 + c4]);
            sB[c4 + 0][r] = vb.x; sB[c4 + 1][r] = vb.y;
            sB[c4 + 2][r] = vb.z; sB[c4 + 3][r] = vb.w;
        }
        __syncthreads();
#pragma unroll
        for (int k = 0; k < BK; k++) {
            float a[8], b[8];
#pragma unroll
            for (int i = 0; i < 8; i++) a[i] = sA[k][ty * 8 + i];
#pragma unroll
            for (int j = 0; j < 8; j++) b[j] = sB[k][tx * 8 + j];
#pragma unroll
            for (int i = 0; i < 8; i++)
#pragma unroll
                for (int j = 0; j < 8; j++) acc[i][j] += a[i] * b[j];
        }
        __syncthreads();
    }

    float bb[8];
#pragma unroll
    for (int j = 0; j < 8; j++) bb[j] = bias[bn + tx * 8 + j];

#pragma unroll
    for (int i = 0; i < 8; i++) {
        size_t row = (size_t)(bm + ty * 8 + i);
#pragma unroll
        for (int j = 0; j < 8; j += 4) {
            int col = bn + tx * 8 + j;
            float4 v;
            v.x = acc[i][j + 0] + bb[j + 0];
            v.y = acc[i][j + 1] + bb[j + 1];
            v.z = acc[i][j + 2] + bb[j + 2];
            v.w = acc[i][j + 3] + bb[j + 3];
            *reinterpret_cast<float4*>(&g_pre[row * Hv + col]) = v;
        }
    }
}

// ---------------------------------------------------------------------------
// Kernel 2: sequential scan. 1 CTA per batch element, 544 threads (17 warps).
// 2 barriers per step; argmax redundantly computed by every warp; softmax
// and embedding gather deferred to post_kernel.
// ---------------------------------------------------------------------------
__global__ __launch_bounds__(544) void scan_kernel(
    const float* __restrict__ emb_table,   // [V, E]
    const float* __restrict__ W1,          // [H, D+E]
    const float* __restrict__ W2,          // [V, H]
    const float* __restrict__ b2,          // [V]
    float* __restrict__ out)
{
    __shared__ float sM[Vv][Hv];     // table @ W1e^T  (34816 B)
    __shared__ float sH[Hv];         // hidden state
    __shared__ float sLogit[20];

    const int b    = blockIdx.x;
    const int tid  = threadIdx.x;
    const int w    = tid >> 5;
    const int lane = tid & 31;

    // Precompute M[v][h] = sum_e table[v][e] * W1[h][D+e]; row 0 zero (padding)
    for (int idx = tid; idx < Vv * Hv; idx += 544) {
        int v = idx / Hv, h = idx - v * Hv;
        float acc = 0.f;
        if (v != 0) {
            const float* er = emb_table + v * Ev;
            const float* wr = W1 + (size_t)h * (Dv + Ev) + Dv;
#pragma unroll 8
            for (int e = 0; e < Ev; e++) acc += er[e] * wr[e];
        }
        sM[v][h] = acc;
    }

    // W2 rows in registers: warp w owns logit w (w is always < 17 here)
    float w2r[16];
#pragma unroll
    for (int k = 0; k < 16; k++) w2r[k] = W2[(size_t)w * Hv + k * 32 + lane];
    const float bias2 = b2[w];
    __syncthreads();

    float* outL = out + OFF_LOGITS;
    float* outP = out + OFF_PREDS;

    const float* preB = g_pre + (size_t)b * Lv * Hv;

    float pcur = (tid < Hv) ? preB[tid] : 0.f;

    for (int t = 0; t < Lv; t++) {
        // prefetch next step's pre slice
        float pnxt = 0.f;
        if (tid < Hv && t + 1 < Lv) pnxt = preB[(size_t)(t + 1) * Hv + tid];

        // stage A: every warp computes argmax of previous step's logits,
        // then its share of the hidden state.
        int pred;
        if (t == 0) {
            pred = 0;   // PAD
        } else {
            float bv = (lane < Vv) ? sLogit[lane] : -1e30f;
            int   bi = (lane < Vv) ? lane : Vv;
#pragma unroll
            for (int off = 16; off; off >>= 1) {
                float ov = __shfl_down_sync(FULLMASK, bv, off);
                int   oi = __shfl_down_sync(FULLMASK, bi, off);
                if (ov > bv || (ov == bv && oi < bi)) { bv = ov; bi = oi; }
            }
            pred = __shfl_sync(FULLMASK, bi, 0);
            if (tid == 0) outP[(size_t)b * Lv + (t - 1)] = (float)pred;
        }
        if (tid < Hv) sH[tid] = tanhf(pcur + sM[pred][tid]);
        __syncthreads();

        // stage B: warp w computes logit[w] = sH . W2[w] + b2[w]
        {
            float acc = 0.f;
#pragma unroll
            for (int k = 0; k < 16; k++) acc += sH[k * 32 + lane] * w2r[k];
#pragma unroll
            for (int off = 16; off; off >>= 1)
                acc += __shfl_xor_sync(FULLMASK, acc, off);
            if (lane == 0) {
                float lg = acc + bias2;
                sLogit[w] = lg;
                outL[((size_t)b * Lv + t) * Vv + w] = lg;
            }
        }
        __syncthreads();

        pcur = pnxt;
    }

    // tail: argmax for the final timestep
    if (w == 0) {
        float bv = (lane < Vv) ? sLogit[lane] : -1e30f;
        int   bi = (lane < Vv) ? lane : Vv;
#pragma unroll
        for (int off = 16; off; off >>= 1) {
            float ov = __shfl_down_sync(FULLMASK, bv, off);
            int   oi = __shfl_down_sync(FULLMASK, bi, off);
            if (ov > bv || (ov == bv && oi < bi)) { bv = ov; bi = oi; }
        }
        if (lane == 0) outP[(size_t)b * Lv + (Lv - 1)] = (float)bi;
    }
}

// ---------------------------------------------------------------------------
// Kernel 3: parallel post-pass — log-softmax from saved logits, preds_emb.
// One warp per (b,t) row.  (Validated correct in R2.)
// ---------------------------------------------------------------------------
__global__ __launch_bounds__(256) void post_kernel(
    const float* __restrict__ emb_table,
    float* __restrict__ out)
{
    const float* outL = out + OFF_LOGITS;
    const float* outP = out + OFF_PREDS;
    float* outQ  = out + OFF_PROBS;
    float* outEb = out + OFF_EMB;

    const int lane = threadIdx.x & 31;
    const int warps_total = (gridDim.x * blockDim.x) >> 5;
    int gw = (blockIdx.x * blockDim.x + threadIdx.x) >> 5;

    for (int row = gw; row < Bv * Lv; row += warps_total) {
        float v = (lane < Vv) ? outL[(size_t)row * Vv + lane] : -1e30f;
        float m = v;
#pragma unroll
        for (int off = 16; off; off >>= 1)
            m = fmaxf(m, __shfl_xor_sync(FULLMASK, m, off));
        float e = (lane < Vv) ? expf(v - m) : 0.f;
        float s = e;
#pragma unroll
        for (int off = 16; off; off >>= 1)
            s += __shfl_xor_sync(FULLMASK, s, off);
        float lse = m + logf(s);
        if (lane < Vv) outQ[(size_t)row * Vv + lane] = v - lse;

        int pred = (int)outP[row];
        float e0 = (pred != 0) ? emb_table[pred * Ev + lane] : 0.f;
        float e1 = (pred != 0) ? emb_table[pred * Ev + 32 + lane] : 0.f;
        outEb[(size_t)row * Ev + lane]      = e0;
        outEb[(size_t)row * Ev + 32 + lane] = e1;
    }
}

// ---------------------------------------------------------------------------
extern "C" void kernel_launch(void* const* d_in, const int* in_sizes, int n_in,
                              void* d_out, int out_size)
{
    const float* inputs    = (const float*)d_in[0];  // [B, L, D]
    const float* emb_table = (const float*)d_in[1];  // [V, E]
    const float* W1        = (const float*)d_in[2];  // [H, D+E]
    const float* b1        = (const float*)d_in[3];  // [H]
    const float* W2        = (const float*)d_in[4];  // [V, H]
    const float* b2        = (const float*)d_in[5];  // [V]
    float* out = (float*)d_out;

    (void)in_sizes; (void)n_in; (void)out_size;

    dim3 ggrid(Hv / 128, (Bv * Lv) / 128);   // (4, 512)
    gemm_pre_kernel<<<ggrid, 256>>>(inputs, W1, b1);

    scan_kernel<<<Bv, 544>>>(emb_table, W1, W2, b2, out);

    post_kernel<<<256, 256>>>(emb_table, out);
}

// round 4
// speedup vs baseline: 1.9158x; 1.0061x over previous
#include <cuda_runtime.h>
#include <cuda_bf16.h>
#include <math.h>

// Problem dims
#define Bv 128
#define Lv 512
#define Dv 512
#define Ev 64
#define Hv 512
#define Vv 17

#define FULLMASK 0xffffffffu

// Output layout (float32 concat of the 4 reference outputs)
#define OFF_LOGITS 0
#define OFF_PREDS  (Bv*Lv*Vv)                 // 1114112
#define OFF_PROBS  (OFF_PREDS + Bv*Lv)        // 1179648
#define OFF_EMB    (OFF_PROBS + Bv*Lv*Vv)     // 2293760

// Scratch: pre[b, t, h] = inputs[b,t,:] @ W1[:, :D]^T + b1   (128 MB)
__device__ float g_pre[(size_t)Bv * Lv * Hv];

// ---------------------------------------------------------------------------
// Kernel 1: pre = A @ W1x^T + b1.  NT-GEMM fp32, 128x128 tile, BK=16,
// double-buffered smem (1 sync per k-tile), vectorized LDS.128 reads.
// ---------------------------------------------------------------------------
__global__ __launch_bounds__(256) void gemm_pre_kernel(
    const float* __restrict__ A, const float* __restrict__ W,
    const float* __restrict__ bias)
{
    constexpr int BM = 128, BN = 128, BK = 16;
    constexpr int NK = Dv / BK;                 // 32 k-tiles
    __shared__ float sA[2][BK][BM + 4];
    __shared__ float sB[2][BK][BN + 4];

    const int bm = blockIdx.y * BM;
    const int bn = blockIdx.x * BN;
    const int tid = threadIdx.x;
    const int tx = tid & 15;       // N direction
    const int ty = tid >> 4;       // M direction

    // gmem->reg staging mapping: slot s*256+tid -> (row r, col group c4)
    const int r0 = tid >> 2;                 // 0..63   (slot = tid)
    const int r1 = (tid + 256) >> 2;         // 64..127 (slot = tid+256)
    const int c4 = (tid & 3) * 4;

    const float* aP0 = A + (size_t)(bm + r0) * Dv + c4;
    const float* aP1 = A + (size_t)(bm + r1) * Dv + c4;
    const float* wP0 = W + (size_t)(bn + r0) * (Dv + Ev) + c4;
    const float* wP1 = W + (size_t)(bn + r1) * (Dv + Ev) + c4;

    float acc[8][8];
#pragma unroll
    for (int i = 0; i < 8; i++)
#pragma unroll
        for (int j = 0; j < 8; j++) acc[i][j] = 0.f;

    // prologue: load tile 0, store to buf 0
    float4 ra0 = *reinterpret_cast<const float4*>(aP0);
    float4 ra1 = *reinterpret_cast<const float4*>(aP1);
    float4 rb0 = *reinterpret_cast<const float4*>(wP0);
    float4 rb1 = *reinterpret_cast<const float4*>(wP1);
    {
        sA[0][c4 + 0][r0] = ra0.x; sA[0][c4 + 1][r0] = ra0.y;
        sA[0][c4 + 2][r0] = ra0.z; sA[0][c4 + 3][r0] = ra0.w;
        sA[0][c4 + 0][r1] = ra1.x; sA[0][c4 + 1][r1] = ra1.y;
        sA[0][c4 + 2][r1] = ra1.z; sA[0][c4 + 3][r1] = ra1.w;
        sB[0][c4 + 0][r0] = rb0.x; sB[0][c4 + 1][r0] = rb0.y;
        sB[0][c4 + 2][r0] = rb0.z; sB[0][c4 + 3][r0] = rb0.w;
        sB[0][c4 + 0][r1] = rb1.x; sB[0][c4 + 1][r1] = rb1.y;
        sB[0][c4 + 2][r1] = rb1.z; sB[0][c4 + 3][r1] = rb1.w;
    }
    __syncthreads();

    for (int ki = 0; ki < NK; ki++) {
        const int cur = ki & 1;
        // prefetch next k-tile into registers
        if (ki + 1 < NK) {
            int k0 = (ki + 1) * BK;
            ra0 = *reinterpret_cast<const float4*>(aP0 + k0);
            ra1 = *reinterpret_cast<const float4*>(aP1 + k0);
            rb0 = *reinterpret_cast<const float4*>(wP0 + k0);
            rb1 = *reinterpret_cast<const float4*>(wP1 + k0);
        }
        // compute from current buffer
#pragma unroll
        for (int k = 0; k < BK; k++) {
            float4 av0 = *reinterpret_cast<const float4*>(&sA[cur][k][ty * 8]);
            float4 av1 = *reinterpret_cast<const float4*>(&sA[cur][k][ty * 8 + 4]);
            float4 bv0 = *reinterpret_cast<const float4*>(&sB[cur][k][tx * 8]);
            float4 bv1 = *reinterpret_cast<const float4*>(&sB[cur][k][tx * 8 + 4]);
            float a[8] = {av0.x, av0.y, av0.z, av0.w, av1.x, av1.y, av1.z, av1.w};
            float b[8] = {bv0.x, bv0.y, bv0.z, bv0.w, bv1.x, bv1.y, bv1.z, bv1.w};
#pragma unroll
            for (int i = 0; i < 8; i++)
#pragma unroll
                for (int j = 0; j < 8; j++) acc[i][j] += a[i] * b[j];
        }
        // stage next tile into the other buffer
        if (ki + 1 < NK) {
            const int nxt = cur ^ 1;
            sA[nxt][c4 + 0][r0] = ra0.x; sA[nxt][c4 + 1][r0] = ra0.y;
            sA[nxt][c4 + 2][r0] = ra0.z; sA[nxt][c4 + 3][r0] = ra0.w;
            sA[nxt][c4 + 0][r1] = ra1.x; sA[nxt][c4 + 1][r1] = ra1.y;
            sA[nxt][c4 + 2][r1] = ra1.z; sA[nxt][c4 + 3][r1] = ra1.w;
            sB[nxt][c4 + 0][r0] = rb0.x; sB[nxt][c4 + 1][r0] = rb0.y;
            sB[nxt][c4 + 2][r0] = rb0.z; sB[nxt][c4 + 3][r0] = rb0.w;
            sB[nxt][c4 + 0][r1] = rb1.x; sB[nxt][c4 + 1][r1] = rb1.y;
            sB[nxt][c4 + 2][r1] = rb1.z; sB[nxt][c4 + 3][r1] = rb1.w;
            __syncthreads();
        }
    }

    float bb[8];
#pragma unroll
    for (int j = 0; j < 8; j++) bb[j] = bias[bn + tx * 8 + j];

#pragma unroll
    for (int i = 0; i < 8; i++) {
        size_t row = (size_t)(bm + ty * 8 + i);
#pragma unroll
        for (int j = 0; j < 8; j += 4) {
            int col = bn + tx * 8 + j;
            float4 v;
            v.x = acc[i][j + 0] + bb[j + 0];
            v.y = acc[i][j + 1] + bb[j + 1];
            v.z = acc[i][j + 2] + bb[j + 2];
            v.w = acc[i][j + 3] + bb[j + 3];
            *reinterpret_cast<float4*>(&g_pre[row * Hv + col]) = v;
        }
    }
}

// ---------------------------------------------------------------------------
// fast warp argmax over lanes [0, Vv): monotone-uint transform + redux.max +
// ballot + ffs.  Uniform result across the warp; first-max tie-break
// (identical to jnp.argmax).
// ---------------------------------------------------------------------------
__device__ __forceinline__ int argmax17(float v, int lane)
{
    unsigned u = __float_as_uint(v);
    u = (u & 0x80000000u) ? ~u : (u | 0x80000000u);   // order-preserving
    if (lane >= Vv) u = 0u;                           // below any real logit
    unsigned mx = __reduce_max_sync(FULLMASK, u);
    unsigned msk = __ballot_sync(FULLMASK, u == mx);
    return __ffs(msk) - 1;
}

// ---------------------------------------------------------------------------
// Kernel 2: sequential scan. 1 CTA per batch element, 544 threads (17 warps).
// 2 barriers per step; redux-based argmax computed by every warp; softmax
// and embedding gather deferred to post_kernel.
// ---------------------------------------------------------------------------
__global__ __launch_bounds__(544) void scan_kernel(
    const float* __restrict__ emb_table,   // [V, E]
    const float* __restrict__ W1,          // [H, D+E]
    const float* __restrict__ W2,          // [V, H]
    const float* __restrict__ b2,          // [V]
    float* __restrict__ out)
{
    __shared__ float sM[Vv][Hv];     // table @ W1e^T  (34816 B)
    __shared__ float sH[Hv];         // hidden state
    __shared__ float sLogit[20];

    const int b    = blockIdx.x;
    const int tid  = threadIdx.x;
    const int w    = tid >> 5;
    const int lane = tid & 31;

    // Precompute M[v][h] = sum_e table[v][e] * W1[h][D+e]; row 0 zero (padding)
    for (int idx = tid; idx < Vv * Hv; idx += 544) {
        int v = idx / Hv, h = idx - v * Hv;
        float acc = 0.f;
        if (v != 0) {
            const float* er = emb_table + v * Ev;
            const float* wr = W1 + (size_t)h * (Dv + Ev) + Dv;
#pragma unroll 8
            for (int e = 0; e < Ev; e++) acc += er[e] * wr[e];
        }
        sM[v][h] = acc;
    }

    // W2 rows in registers: warp w owns logit w (w is always < 17 here)
    float w2r[16];
#pragma unroll
    for (int k = 0; k < 16; k++) w2r[k] = W2[(size_t)w * Hv + k * 32 + lane];
    const float bias2 = b2[w];
    __syncthreads();

    float* outL = out + OFF_LOGITS;
    float* outP = out + OFF_PREDS;

    const float* preB = g_pre + (size_t)b * Lv * Hv;

    float pcur = (tid < Hv) ? preB[tid] : 0.f;

    for (int t = 0; t < Lv; t++) {
        // prefetch next step's pre slice
        float pnxt = 0.f;
        if (tid < Hv && t + 1 < Lv) pnxt = preB[(size_t)(t + 1) * Hv + tid];

        // stage A: every warp computes argmax of previous step's logits,
        // then its share of the hidden state.
        int pred;
        if (t == 0) {
            pred = 0;   // PAD
        } else {
            pred = argmax17((lane < Vv) ? sLogit[lane] : 0.f, lane);
            if (tid == 0) outP[(size_t)b * Lv + (t - 1)] = (float)pred;
        }
        if (tid < Hv) sH[tid] = tanhf(pcur + sM[pred][tid]);
        __syncthreads();

        // stage B: warp w computes logit[w] = sH . W2[w] + b2[w]
        {
            float acc = 0.f;
#pragma unroll
            for (int k = 0; k < 16; k++) acc += sH[k * 32 + lane] * w2r[k];
#pragma unroll
            for (int off = 16; off; off >>= 1)
                acc += __shfl_xor_sync(FULLMASK, acc, off);
            if (lane == 0) {
                float lg = acc + bias2;
                sLogit[w] = lg;
                outL[((size_t)b * Lv + t) * Vv + w] = lg;
            }
        }
        __syncthreads();

        pcur = pnxt;
    }

    // tail: argmax for the final timestep
    if (w == 0) {
        int pred = argmax17((lane < Vv) ? sLogit[lane] : 0.f, lane);
        if (lane == 0) outP[(size_t)b * Lv + (Lv - 1)] = (float)pred;
    }
}

// ---------------------------------------------------------------------------
// Kernel 3: parallel post-pass — log-softmax from saved logits, preds_emb.
// One warp per (b,t) row.
// ---------------------------------------------------------------------------
__global__ __launch_bounds__(256) void post_kernel(
    const float* __restrict__ emb_table,
    float* __restrict__ out)
{
    const float* outL = out + OFF_LOGITS;
    const float* outP = out + OFF_PREDS;
    float* outQ  = out + OFF_PROBS;
    float* outEb = out + OFF_EMB;

    const int lane = threadIdx.x & 31;
    const int warps_total = (gridDim.x * blockDim.x) >> 5;
    int gw = (blockIdx.x * blockDim.x + threadIdx.x) >> 5;

    for (int row = gw; row < Bv * Lv; row += warps_total) {
        float v = (lane < Vv) ? outL[(size_t)row * Vv + lane] : -1e30f;
        float m = v;
#pragma unroll
        for (int off = 16; off; off >>= 1)
            m = fmaxf(m, __shfl_xor_sync(FULLMASK, m, off));
        float e = (lane < Vv) ? expf(v - m) : 0.f;
        float s = e;
#pragma unroll
        for (int off = 16; off; off >>= 1)
            s += __shfl_xor_sync(FULLMASK, s, off);
        float lse = m + logf(s);
        if (lane < Vv) outQ[(size_t)row * Vv + lane] = v - lse;

        int pred = (int)outP[row];
        float e0 = (pred != 0) ? emb_table[pred * Ev + lane] : 0.f;
        float e1 = (pred != 0) ? emb_table[pred * Ev + 32 + lane] : 0.f;
        outEb[(size_t)row * Ev + lane]      = e0;
        outEb[(size_t)row * Ev + 32 + lane] = e1;
    }
}

// ---------------------------------------------------------------------------
extern "C" void kernel_launch(void* const* d_in, const int* in_sizes, int n_in,
                              void* d_out, int out_size)
{
    const float* inputs    = (const float*)d_in[0];  // [B, L, D]
    const float* emb_table = (const float*)d_in[1];  // [V, E]
    const float* W1        = (const float*)d_in[2];  // [H, D+E]
    const float* b1        = (const float*)d_in[3];  // [H]
    const float* W2        = (const float*)d_in[4];  // [V, H]
    const float* b2        = (const float*)d_in[5];  // [V]
    float* out = (float*)d_out;

    (void)in_sizes; (void)n_in; (void)out_size;

    dim3 ggrid(Hv / 128, (Bv * Lv) / 128);   // (4, 512)
    gemm_pre_kernel<<<ggrid, 256>>>(inputs, W1, b1);

    scan_kernel<<<Bv, 544>>>(emb_table, W1, W2, b2, out);

    post_kernel<<<256, 256>>>(emb_table, out);
}